// round 13
// baseline (speedup 1.0000x reference)
#include <cuda_runtime.h>
#include <cuda_bf16.h>

// Problem constants (match reference_code)
#define NN 50000
#define EE 600000
#define FF 128   // F_IN == F_OUT == 128

// ---------------------------------------------------------------------------
// Device-global scratch (allocation-free scratch mechanism)
// ---------------------------------------------------------------------------
__device__ int g_count[NN];        // histogram of dst
__device__ int g_cursor[NN];       // running cursor for reorder
__device__ int g_off[NN + 1];      // CSR row pointers (by dst)
__device__ int g_src[EE];          // src indices sorted by dst
__device__ int g_is64;             // 1 if edge_index is int64, 0 if int32

typedef unsigned long long u64;

// Packed fp32x2 helpers (ptxas never emits FFMA2 from plain C++)
__device__ __forceinline__ u64 pk2(float lo, float hi) {
    u64 r;
    asm("mov.b64 %0, {%1, %2};" : "=l"(r) : "f"(lo), "f"(hi));
    return r;
}
__device__ __forceinline__ void upk2(float& lo, float& hi, u64 v) {
    asm("mov.b64 {%0, %1}, %2;" : "=f"(lo), "=f"(hi) : "l"(v));
}
__device__ __forceinline__ void fma2(u64& d, u64 a, u64 b) {
    asm("fma.rn.f32x2 %0, %1, %2, %0;" : "+l"(d) : "l"(a), "l"(b));
}

// Read one edge endpoint under either index width
__device__ __forceinline__ int read_idx(const void* eiv, long long pos, int is64) {
    if (is64) return (int)((const long long*)eiv)[pos];
    return ((const int*)eiv)[pos];
}

// ---------------------------------------------------------------------------
// Kernel A: zero the histogram; block 0 also detects index width.
// int64 values < 50000 => all odd 32-bit words zero; int32 => random ids.
// ---------------------------------------------------------------------------
__global__ void zero_detect_kernel(const unsigned int* __restrict__ ei_w) {
    int i = blockIdx.x * blockDim.x + threadIdx.x;
    if (i < NN) g_count[i] = 0;

    if (blockIdx.x == 0) {
        __shared__ unsigned int red[256];
        unsigned int acc = 0;
        for (int s = threadIdx.x; s < 2048; s += 256)
            acc |= ei_w[2 * s + 1];
        red[threadIdx.x] = acc;
        __syncthreads();
        for (int s = 128; s > 0; s >>= 1) {
            if (threadIdx.x < s) red[threadIdx.x] |= red[threadIdx.x + s];
            __syncthreads();
        }
        if (threadIdx.x == 0) g_is64 = (red[0] == 0u) ? 1 : 0;
    }
}

// ---------------------------------------------------------------------------
// Kernel B: histogram of dst
// ---------------------------------------------------------------------------
__global__ void hist_kernel(const void* __restrict__ eiv) {
    int e = blockIdx.x * blockDim.x + threadIdx.x;
    if (e >= EE) return;
    int dst = read_idx(eiv, (long long)EE + e, g_is64);
    if ((unsigned)dst < NN) atomicAdd(&g_count[dst], 1);
}

// ---------------------------------------------------------------------------
// Kernel C: exclusive prefix sum over g_count -> g_off, g_cursor.
// Single CTA, 1024 threads, ITEMS=49 contiguous elements each.
// ---------------------------------------------------------------------------
#define SCAN_ITEMS 49
__global__ __launch_bounds__(1024, 1)
void scan_kernel() {
    int tid = threadIdx.x;
    int base = tid * SCAN_ITEMS;

    int sum = 0;
    #pragma unroll
    for (int i = 0; i < SCAN_ITEMS; i++) {
        int idx = base + i;
        if (idx < NN) sum += g_count[idx];
    }

    __shared__ int s[1024];
    s[tid] = sum;
    __syncthreads();
    // Hillis-Steele inclusive scan (read-before-write per step)
    for (int off = 1; off < 1024; off <<= 1) {
        int v = (tid >= off) ? s[tid - off] : 0;
        __syncthreads();
        s[tid] += v;
        __syncthreads();
    }
    int run = (tid > 0) ? s[tid - 1] : 0;  // exclusive prefix of this chunk

    #pragma unroll
    for (int i = 0; i < SCAN_ITEMS; i++) {
        int idx = base + i;
        if (idx < NN) {
            g_off[idx]    = run;
            g_cursor[idx] = run;
            run += g_count[idx];
        }
    }
    if (tid == 0) g_off[NN] = EE;
}

// ---------------------------------------------------------------------------
// Kernel D: reorder src indices into dst-sorted order
// ---------------------------------------------------------------------------
__global__ void reorder_kernel(const void* __restrict__ eiv) {
    int e = blockIdx.x * blockDim.x + threadIdx.x;
    if (e >= EE) return;
    int is64 = g_is64;
    int src = read_idx(eiv, e, is64);
    int dst = read_idx(eiv, (long long)EE + e, is64);
    if ((unsigned)src >= NN || (unsigned)dst >= NN) return;
    int pos = atomicAdd(&g_cursor[dst], 1);
    g_src[pos] = src;
}

// ---------------------------------------------------------------------------
// Kernel E: fused gather + GEMM.
// CTA = 64 dst rows, 256 threads. Warp w gathers rows w*8..w*8+7 into smem
// (register accumulation, unroll-4 for MLP), then the same warp consumes
// exactly those rows in the FFMA2 GEMM tile. out = gathered @ W2 + b2.
// Smem: A 64x128 (32 KB) + W2 128x128 (64 KB) = 96 KB.
// ---------------------------------------------------------------------------
#define GEMM_ROWS 64

__global__ __launch_bounds__(256, 2)
void fused_kernel(const float* __restrict__ x,
                  const float* __restrict__ W2,
                  const float* __restrict__ b2,
                  float* __restrict__ out) {
    extern __shared__ float smem[];
    float* a_s = smem;                    // [64][128]
    float* w_s = smem + GEMM_ROWS * FF;   // [128][128]

    int tid  = threadIdx.x;
    int lane = tid & 31;
    int w    = tid >> 5;                  // warp 0..7 (= ty in GEMM)
    int row0 = blockIdx.x * GEMM_ROWS;

    // Stage W2 into smem (4096 float4, 16 per thread)
    {
        const float4* w4g = reinterpret_cast<const float4*>(W2);
        float4* w4s = reinterpret_cast<float4*>(w_s);
        #pragma unroll
        for (int it = 0; it < (FF * FF / 4) / 256; it++) {
            int idx = tid + it * 256;
            w4s[idx] = w4g[idx];
        }
    }

    // Gather: warp w accumulates its 8 rows; lane owns cols 4*lane..4*lane+3
    const float4* x4 = reinterpret_cast<const float4*>(x);
    #pragma unroll
    for (int j = 0; j < 8; j++) {
        int r  = w * 8 + j;
        int gr = row0 + r;
        float4 a0 = make_float4(0.f, 0.f, 0.f, 0.f);
        float4 a1 = a0, a2 = a0, a3 = a0;
        if (gr < NN) {
            int beg = g_off[gr];
            int end = g_off[gr + 1];
            int e = beg;
            for (; e + 4 <= end; e += 4) {
                int s0 = g_src[e], s1 = g_src[e + 1];
                int s2 = g_src[e + 2], s3 = g_src[e + 3];
                float4 v0 = x4[(size_t)s0 * 32 + lane];
                float4 v1 = x4[(size_t)s1 * 32 + lane];
                float4 v2 = x4[(size_t)s2 * 32 + lane];
                float4 v3 = x4[(size_t)s3 * 32 + lane];
                a0.x += v0.x; a0.y += v0.y; a0.z += v0.z; a0.w += v0.w;
                a1.x += v1.x; a1.y += v1.y; a1.z += v1.z; a1.w += v1.w;
                a2.x += v2.x; a2.y += v2.y; a2.z += v2.z; a2.w += v2.w;
                a3.x += v3.x; a3.y += v3.y; a3.z += v3.z; a3.w += v3.w;
            }
            for (; e < end; e++) {
                int s = g_src[e];
                float4 v = x4[(size_t)s * 32 + lane];
                a0.x += v.x; a0.y += v.y; a0.z += v.z; a0.w += v.w;
            }
        }
        float4 acc;
        acc.x = (a0.x + a1.x) + (a2.x + a3.x);
        acc.y = (a0.y + a1.y) + (a2.y + a3.y);
        acc.z = (a0.z + a1.z) + (a2.z + a3.z);
        acc.w = (a0.w + a1.w) + (a2.w + a3.w);
        reinterpret_cast<float4*>(a_s)[r * 32 + lane] = acc;
    }
    __syncthreads();

    // GEMM: thread (tx=lane, ty=w): cols 4*tx..4*tx+3, rows ty*8..ty*8+7
    int tx = lane, ty = w;
    u64 acc[8][2];
    #pragma unroll
    for (int j = 0; j < 8; j++) {
        acc[j][0] = pk2(0.f, 0.f);
        acc[j][1] = pk2(0.f, 0.f);
    }

    const float4* a4s = reinterpret_cast<const float4*>(a_s);
    const float4* w4s = reinterpret_cast<const float4*>(w_s);

    #pragma unroll 4
    for (int k = 0; k < FF; k += 4) {
        float4 wv0 = w4s[(k + 0) * 32 + tx];
        float4 wv1 = w4s[(k + 1) * 32 + tx];
        float4 wv2 = w4s[(k + 2) * 32 + tx];
        float4 wv3 = w4s[(k + 3) * 32 + tx];
        u64 w0lo = pk2(wv0.x, wv0.y), w0hi = pk2(wv0.z, wv0.w);
        u64 w1lo = pk2(wv1.x, wv1.y), w1hi = pk2(wv1.z, wv1.w);
        u64 w2lo = pk2(wv2.x, wv2.y), w2hi = pk2(wv2.z, wv2.w);
        u64 w3lo = pk2(wv3.x, wv3.y), w3hi = pk2(wv3.z, wv3.w);

        #pragma unroll
        for (int j = 0; j < 8; j++) {
            int r = ty * 8 + j;
            float4 av = a4s[r * 32 + (k >> 2)];
            u64 ax = pk2(av.x, av.x);
            u64 ay = pk2(av.y, av.y);
            u64 az = pk2(av.z, av.z);
            u64 aw = pk2(av.w, av.w);
            fma2(acc[j][0], ax, w0lo);  fma2(acc[j][1], ax, w0hi);
            fma2(acc[j][0], ay, w1lo);  fma2(acc[j][1], ay, w1hi);
            fma2(acc[j][0], az, w2lo);  fma2(acc[j][1], az, w2hi);
            fma2(acc[j][0], aw, w3lo);  fma2(acc[j][1], aw, w3hi);
        }
    }

    // Epilogue: + b2, write float4
    float4 bias = reinterpret_cast<const float4*>(b2)[tx];
    #pragma unroll
    for (int j = 0; j < 8; j++) {
        int gr = row0 + ty * 8 + j;
        if (gr < NN) {
            float4 o;
            upk2(o.x, o.y, acc[j][0]);
            upk2(o.z, o.w, acc[j][1]);
            o.x += bias.x; o.y += bias.y; o.z += bias.z; o.w += bias.w;
            reinterpret_cast<float4*>(out)[(size_t)gr * 32 + tx] = o;
        }
    }
}

// ---------------------------------------------------------------------------
// Launch: zero+detect -> hist -> scan -> reorder -> fused gather+GEMM
// Inputs (metadata order): x, edge_index, edge_weight, W1, b1, W2, b2, a, b
// ---------------------------------------------------------------------------
extern "C" void kernel_launch(void* const* d_in, const int* in_sizes, int n_in,
                              void* d_out, int out_size) {
    const float* x   = (const float*)d_in[0];
    const void*  ei  = d_in[1];
    const float* W2  = (const float*)d_in[5];
    const float* b2  = (const float*)d_in[6];
    float*       out = (float*)d_out;

    zero_detect_kernel<<<(NN + 255) / 256, 256>>>((const unsigned int*)ei);

    hist_kernel<<<(EE + 255) / 256, 256>>>(ei);

    scan_kernel<<<1, 1024>>>();

    reorder_kernel<<<(EE + 255) / 256, 256>>>(ei);

    {
        int smem_bytes = (GEMM_ROWS * FF + FF * FF) * sizeof(float);  // 96 KB
        cudaFuncSetAttribute(fused_kernel,
                             cudaFuncAttributeMaxDynamicSharedMemorySize,
                             smem_bytes);
        int blocks = (NN + GEMM_ROWS - 1) / GEMM_ROWS;  // 782
        fused_kernel<<<blocks, 256, smem_bytes>>>(x, W2, b2, out);
    }
}

// round 15
// speedup vs baseline: 1.0078x; 1.0078x over previous
#include <cuda_runtime.h>
#include <cuda_bf16.h>

// Problem constants (match reference_code)
#define NN 50000
#define EE 600000
#define FF 128   // F_IN == F_OUT == 128

// ---------------------------------------------------------------------------
// Device-global scratch (allocation-free scratch mechanism)
// ---------------------------------------------------------------------------
__device__ int g_count[NN];        // histogram of dst
__device__ int g_cursor[NN];       // running cursor for reorder
__device__ int g_off[NN + 1];      // CSR row pointers (by dst)
__device__ int g_src[EE];          // src indices sorted by dst
__device__ int g_is64;             // 1 if edge_index is int64, 0 if int32

typedef unsigned long long u64;

// Packed fp32x2 helpers (ptxas never emits FFMA2 from plain C++)
__device__ __forceinline__ u64 pk2(float lo, float hi) {
    u64 r;
    asm("mov.b64 %0, {%1, %2};" : "=l"(r) : "f"(lo), "f"(hi));
    return r;
}
__device__ __forceinline__ void upk2(float& lo, float& hi, u64 v) {
    asm("mov.b64 {%0, %1}, %2;" : "=f"(lo), "=f"(hi) : "l"(v));
}
__device__ __forceinline__ void fma2(u64& d, u64 a, u64 b) {
    asm("fma.rn.f32x2 %0, %1, %2, %0;" : "+l"(d) : "l"(a), "l"(b));
}

// Read one edge endpoint under either index width
__device__ __forceinline__ int read_idx(const void* eiv, long long pos, int is64) {
    if (is64) return (int)((const long long*)eiv)[pos];
    return ((const int*)eiv)[pos];
}

// ---------------------------------------------------------------------------
// Kernel A: zero the histogram; block 0 also detects index width.
// ---------------------------------------------------------------------------
__global__ void zero_detect_kernel(const unsigned int* __restrict__ ei_w) {
    int i = blockIdx.x * blockDim.x + threadIdx.x;
    if (i < NN) g_count[i] = 0;

    if (blockIdx.x == 0) {
        __shared__ unsigned int red[256];
        unsigned int acc = 0;
        for (int s = threadIdx.x; s < 2048; s += 256)
            acc |= ei_w[2 * s + 1];
        red[threadIdx.x] = acc;
        __syncthreads();
        for (int s = 128; s > 0; s >>= 1) {
            if (threadIdx.x < s) red[threadIdx.x] |= red[threadIdx.x + s];
            __syncthreads();
        }
        if (threadIdx.x == 0) g_is64 = (red[0] == 0u) ? 1 : 0;
    }
}

// ---------------------------------------------------------------------------
// Kernel B: histogram of dst
// ---------------------------------------------------------------------------
__global__ void hist_kernel(const void* __restrict__ eiv) {
    int e = blockIdx.x * blockDim.x + threadIdx.x;
    if (e >= EE) return;
    int dst = read_idx(eiv, (long long)EE + e, g_is64);
    if ((unsigned)dst < NN) atomicAdd(&g_count[dst], 1);
}

// ---------------------------------------------------------------------------
// Kernel C: exclusive prefix sum over g_count -> g_off, g_cursor.
// ---------------------------------------------------------------------------
#define SCAN_ITEMS 49
__global__ __launch_bounds__(1024, 1)
void scan_kernel() {
    int tid = threadIdx.x;
    int base = tid * SCAN_ITEMS;

    int sum = 0;
    #pragma unroll
    for (int i = 0; i < SCAN_ITEMS; i++) {
        int idx = base + i;
        if (idx < NN) sum += g_count[idx];
    }

    __shared__ int s[1024];
    s[tid] = sum;
    __syncthreads();
    for (int off = 1; off < 1024; off <<= 1) {
        int v = (tid >= off) ? s[tid - off] : 0;
        __syncthreads();
        s[tid] += v;
        __syncthreads();
    }
    int run = (tid > 0) ? s[tid - 1] : 0;

    #pragma unroll
    for (int i = 0; i < SCAN_ITEMS; i++) {
        int idx = base + i;
        if (idx < NN) {
            g_off[idx]    = run;
            g_cursor[idx] = run;
            run += g_count[idx];
        }
    }
    if (tid == 0) g_off[NN] = EE;
}

// ---------------------------------------------------------------------------
// Kernel D: reorder src indices into dst-sorted order
// ---------------------------------------------------------------------------
__global__ void reorder_kernel(const void* __restrict__ eiv) {
    int e = blockIdx.x * blockDim.x + threadIdx.x;
    if (e >= EE) return;
    int is64 = g_is64;
    int src = read_idx(eiv, e, is64);
    int dst = read_idx(eiv, (long long)EE + e, is64);
    if ((unsigned)src >= NN || (unsigned)dst >= NN) return;
    int pos = atomicAdd(&g_cursor[dst], 1);
    g_src[pos] = src;
}

// ---------------------------------------------------------------------------
// Kernel E: fused segmented gather + GEMM.
// CTA = 64 dst rows, 256 threads. Warp w owns rows r0=blk*64+w*8 .. r0+7,
// whose edges form ONE contiguous range of g_src. The warp streams that
// range in chunks of 8 (8 independent g_src loads + 8 independent LDG.128
// of x per chunk => high MLP), accumulating in a register float4 and
// flushing to the smem A-tile on row boundaries (plain STS, exclusive
// ownership, warp-uniform control flow, offsets shuffled from lanes 0..8).
// Then the verified FFMA2 GEMM consumes the tile: out = A @ W2 + b2.
// ---------------------------------------------------------------------------
#define GEMM_ROWS 64

__global__ __launch_bounds__(256, 2)
void fused_kernel(const float* __restrict__ x,
                  const float* __restrict__ W2,
                  const float* __restrict__ b2,
                  float* __restrict__ out) {
    extern __shared__ float smem[];
    float* a_s = smem;                    // [64][128]
    float* w_s = smem + GEMM_ROWS * FF;   // [128][128]

    int tid  = threadIdx.x;
    int lane = tid & 31;
    int w    = tid >> 5;                  // warp 0..7 (= ty in GEMM)
    int row0 = blockIdx.x * GEMM_ROWS;

    // Stage W2 into smem first (independent loads overlap the gather chain)
    {
        const float4* w4g = reinterpret_cast<const float4*>(W2);
        float4* w4s = reinterpret_cast<float4*>(w_s);
        #pragma unroll
        for (int it = 0; it < (FF * FF / 4) / 256; it++) {
            int idx = tid + it * 256;
            w4s[idx] = w4g[idx];
        }
    }

    // ---- Segmented gather: warp w streams edges of rows r0..r0+7 ----
    {
        const float4* x4 = reinterpret_cast<const float4*>(x);
        float4* a4s = reinterpret_cast<float4*>(a_s);
        int r0 = row0 + w * 8;

        // lanes 0..8 hold g_off[r0+lane] (clamped); others unused
        int ci = r0 + lane;
        if (ci > NN) ci = NN;
        int off_l = (lane <= 8) ? g_off[ci] : 0;

        int beg     = __shfl_sync(0xffffffffu, off_l, 0);
        int end     = __shfl_sync(0xffffffffu, off_l, 8);
        int cur     = 0;                                  // row within group
        int row_end = __shfl_sync(0xffffffffu, off_l, 1);
        float4 acc  = make_float4(0.f, 0.f, 0.f, 0.f);

        int e = beg;
        while (e < end) {
            int cnt = end - e;
            if (cnt > 8) cnt = 8;

            int sidx[8];
            #pragma unroll
            for (int i = 0; i < 8; i++)
                sidx[i] = (i < cnt) ? g_src[e + i] : 0;

            float4 v[8];
            #pragma unroll
            for (int i = 0; i < 8; i++)
                v[i] = (i < cnt) ? x4[(size_t)sidx[i] * 32 + lane]
                                 : make_float4(0.f, 0.f, 0.f, 0.f);

            #pragma unroll
            for (int i = 0; i < 8; i++) {
                if (i < cnt) {
                    while (e + i >= row_end) {            // warp-uniform
                        a4s[(w * 8 + cur) * 32 + lane] = acc;
                        acc = make_float4(0.f, 0.f, 0.f, 0.f);
                        cur++;
                        row_end = __shfl_sync(0xffffffffu, off_l, cur + 1);
                    }
                    acc.x += v[i].x; acc.y += v[i].y;
                    acc.z += v[i].z; acc.w += v[i].w;
                }
            }
            e += cnt;
        }
        // trailing flush: current row gets acc, remaining rows get zeros
        while (cur < 8) {
            a4s[(w * 8 + cur) * 32 + lane] = acc;
            acc = make_float4(0.f, 0.f, 0.f, 0.f);
            cur++;
        }
    }
    __syncthreads();

    // ---- GEMM: thread (tx=lane, ty=w): cols 4*tx..4*tx+3, rows ty*8..+7 ----
    int tx = lane, ty = w;
    u64 acc[8][2];
    #pragma unroll
    for (int j = 0; j < 8; j++) {
        acc[j][0] = pk2(0.f, 0.f);
        acc[j][1] = pk2(0.f, 0.f);
    }

    const float4* a4s = reinterpret_cast<const float4*>(a_s);
    const float4* w4s = reinterpret_cast<const float4*>(w_s);

    #pragma unroll 4
    for (int k = 0; k < FF; k += 4) {
        float4 wv0 = w4s[(k + 0) * 32 + tx];
        float4 wv1 = w4s[(k + 1) * 32 + tx];
        float4 wv2 = w4s[(k + 2) * 32 + tx];
        float4 wv3 = w4s[(k + 3) * 32 + tx];
        u64 w0lo = pk2(wv0.x, wv0.y), w0hi = pk2(wv0.z, wv0.w);
        u64 w1lo = pk2(wv1.x, wv1.y), w1hi = pk2(wv1.z, wv1.w);
        u64 w2lo = pk2(wv2.x, wv2.y), w2hi = pk2(wv2.z, wv2.w);
        u64 w3lo = pk2(wv3.x, wv3.y), w3hi = pk2(wv3.z, wv3.w);

        #pragma unroll
        for (int j = 0; j < 8; j++) {
            int r = ty * 8 + j;
            float4 av = a4s[r * 32 + (k >> 2)];
            u64 ax = pk2(av.x, av.x);
            u64 ay = pk2(av.y, av.y);
            u64 az = pk2(av.z, av.z);
            u64 aw = pk2(av.w, av.w);
            fma2(acc[j][0], ax, w0lo);  fma2(acc[j][1], ax, w0hi);
            fma2(acc[j][0], ay, w1lo);  fma2(acc[j][1], ay, w1hi);
            fma2(acc[j][0], az, w2lo);  fma2(acc[j][1], az, w2hi);
            fma2(acc[j][0], aw, w3lo);  fma2(acc[j][1], aw, w3hi);
        }
    }

    // Epilogue: + b2, write float4
    float4 bias = reinterpret_cast<const float4*>(b2)[tx];
    #pragma unroll
    for (int j = 0; j < 8; j++) {
        int gr = row0 + ty * 8 + j;
        if (gr < NN) {
            float4 o;
            upk2(o.x, o.y, acc[j][0]);
            upk2(o.z, o.w, acc[j][1]);
            o.x += bias.x; o.y += bias.y; o.z += bias.z; o.w += bias.w;
            reinterpret_cast<float4*>(out)[(size_t)gr * 32 + tx] = o;
        }
    }
}

// ---------------------------------------------------------------------------
// Launch: zero+detect -> hist -> scan -> reorder -> fused gather+GEMM
// Inputs (metadata order): x, edge_index, edge_weight, W1, b1, W2, b2, a, b
// ---------------------------------------------------------------------------
extern "C" void kernel_launch(void* const* d_in, const int* in_sizes, int n_in,
                              void* d_out, int out_size) {
    const float* x   = (const float*)d_in[0];
    const void*  ei  = d_in[1];
    const float* W2  = (const float*)d_in[5];
    const float* b2  = (const float*)d_in[6];
    float*       out = (float*)d_out;

    zero_detect_kernel<<<(NN + 255) / 256, 256>>>((const unsigned int*)ei);

    hist_kernel<<<(EE + 255) / 256, 256>>>(ei);

    scan_kernel<<<1, 1024>>>();

    reorder_kernel<<<(EE + 255) / 256, 256>>>(ei);

    {
        int smem_bytes = (GEMM_ROWS * FF + FF * FF) * sizeof(float);  // 96 KB
        cudaFuncSetAttribute(fused_kernel,
                             cudaFuncAttributeMaxDynamicSharedMemorySize,
                             smem_bytes);
        int blocks = (NN + GEMM_ROWS - 1) / GEMM_ROWS;  // 782
        fused_kernel<<<blocks, 256, smem_bytes>>>(x, W2, b2, out);
    }
}

// round 17
// speedup vs baseline: 1.8580x; 1.8436x over previous
#include <cuda_runtime.h>
#include <cuda_bf16.h>

// Problem constants (match reference_code)
#define NN 50000
#define EE 600000
#define FF 128   // F_IN == F_OUT == 128

// ---------------------------------------------------------------------------
// Device-global scratch (allocation-free scratch mechanism)
// ---------------------------------------------------------------------------
__device__ int   g_head[NN];                  // per-dst list head (edge id or -1)
__device__ int   g_next[EE];                  // next edge in dst's list
__device__ float g_agg[(size_t)NN * FF];      // gathered features (25.6 MB)
__device__ int   g_is64;                      // 1 if edge_index int64, else int32

typedef unsigned long long u64;

// Packed fp32x2 helpers (ptxas never emits FFMA2 from plain C++)
__device__ __forceinline__ u64 pk2(float lo, float hi) {
    u64 r;
    asm("mov.b64 %0, {%1, %2};" : "=l"(r) : "f"(lo), "f"(hi));
    return r;
}
__device__ __forceinline__ void upk2(float& lo, float& hi, u64 v) {
    asm("mov.b64 {%0, %1}, %2;" : "=f"(lo), "=f"(hi) : "l"(v));
}
__device__ __forceinline__ void fma2(u64& d, u64 a, u64 b) {
    asm("fma.rn.f32x2 %0, %1, %2, %0;" : "+l"(d) : "l"(a), "l"(b));
}

// Read one edge endpoint under either index width
__device__ __forceinline__ int read_idx(const void* eiv, long long pos, int is64) {
    if (is64) return (int)((const long long*)eiv)[pos];
    return ((const int*)eiv)[pos];
}

// ---------------------------------------------------------------------------
// Kernel A: init head[] = -1; block 0 also detects index width.
// int64 values < 50000 => all odd 32-bit words zero; int32 => random ids.
// ---------------------------------------------------------------------------
__global__ void init_detect_kernel(const unsigned int* __restrict__ ei_w) {
    int i = blockIdx.x * blockDim.x + threadIdx.x;
    if (i < NN) g_head[i] = -1;

    if (blockIdx.x == 0) {
        __shared__ unsigned int red[256];
        unsigned int acc = 0;
        for (int s = threadIdx.x; s < 2048; s += 256)
            acc |= ei_w[2 * s + 1];
        red[threadIdx.x] = acc;
        __syncthreads();
        for (int s = 128; s > 0; s >>= 1) {
            if (threadIdx.x < s) red[threadIdx.x] |= red[threadIdx.x + s];
            __syncthreads();
        }
        if (threadIdx.x == 0) g_is64 = (red[0] == 0u) ? 1 : 0;
    }
}

// ---------------------------------------------------------------------------
// Kernel B: build per-dst linked lists in ONE pass (no hist/scan/reorder).
// ---------------------------------------------------------------------------
__global__ void link_kernel(const void* __restrict__ eiv) {
    int e = blockIdx.x * blockDim.x + threadIdx.x;
    if (e >= EE) return;
    int dst = read_idx(eiv, (long long)EE + e, g_is64);
    if ((unsigned)dst >= NN) return;           // never on valid data
    int old = atomicExch(&g_head[dst], e);
    g_next[e] = old;
}

// ---------------------------------------------------------------------------
// Kernel C: gather. One warp handles 4 independent rows (4 concurrent
// pointer chains => 4x MLP on the chain-serial next[] loads). Lane l owns
// feature quad 4l..4l+3. Chain loads (next, src) are warp-uniform
// broadcasts; x row loads are 512B coalesced LDG.128 and hang off the
// chain without blocking it. Each row is written ONCE (no RMW, no zeroing).
// ---------------------------------------------------------------------------
#define ROWS_PER_WARP 4
#define GATHER_SPAN (NN / ROWS_PER_WARP)      // 12500

__global__ __launch_bounds__(256)
void gather_kernel(const float* __restrict__ x,
                   const void* __restrict__ eiv,
                   float* __restrict__ agg) {
    int warp = (blockIdx.x * blockDim.x + threadIdx.x) >> 5;
    int lane = threadIdx.x & 31;
    if (warp >= GATHER_SPAN) return;
    int is64 = g_is64;

    const float4* x4 = reinterpret_cast<const float4*>(x);
    float4* agg4 = reinterpret_cast<float4*>(agg);

    int    e[ROWS_PER_WARP];
    float4 acc[ROWS_PER_WARP];
    #pragma unroll
    for (int c = 0; c < ROWS_PER_WARP; c++) {
        e[c]   = g_head[warp + c * GATHER_SPAN];
        acc[c] = make_float4(0.f, 0.f, 0.f, 0.f);
    }

    bool any = true;
    while (any) {
        any = false;
        #pragma unroll
        for (int c = 0; c < ROWS_PER_WARP; c++) {
            if (e[c] >= 0) {
                int nxt = g_next[e[c]];                      // chain-serial (4B)
                int src = read_idx(eiv, e[c], is64);         // off-chain
                float4 v = x4[(size_t)src * 32 + lane];      // off-chain, 512B
                acc[c].x += v.x; acc[c].y += v.y;
                acc[c].z += v.z; acc[c].w += v.w;
                e[c] = nxt;
                any = true;
            }
        }
    }

    #pragma unroll
    for (int c = 0; c < ROWS_PER_WARP; c++)
        agg4[(size_t)(warp + c * GATHER_SPAN) * 32 + lane] = acc[c];
}

// ---------------------------------------------------------------------------
// Kernel D: out[N,128] = agg[N,128] @ W2[128,128] + b2   (verified R8 FFMA2)
// Block: 256 threads, 64 rows. Smem: A 64x128 + W2 128x128 = 96 KB.
// ---------------------------------------------------------------------------
#define GEMM_ROWS 64

__global__ __launch_bounds__(256, 2)
void gemm_kernel(const float* __restrict__ agg,
                 const float* __restrict__ W2,
                 const float* __restrict__ b2,
                 float* __restrict__ out) {
    extern __shared__ float smem[];
    float* a_s = smem;                    // [64][128]
    float* w_s = smem + GEMM_ROWS * FF;   // [128][128]

    int tid = threadIdx.x;
    int tx  = tid & 31;
    int ty  = tid >> 5;
    int row0 = blockIdx.x * GEMM_ROWS;

    // Load A-tile (2048 float4)
    {
        const float4* a4g = reinterpret_cast<const float4*>(agg);
        float4* a4s = reinterpret_cast<float4*>(a_s);
        #pragma unroll
        for (int it = 0; it < (GEMM_ROWS * FF / 4) / 256; it++) {
            int idx = tid + it * 256;
            int r   = idx >> 5;
            int c4  = idx & 31;
            int gr  = row0 + r;
            float4 v = make_float4(0.f, 0.f, 0.f, 0.f);
            if (gr < NN) v = a4g[(size_t)gr * 32 + c4];
            a4s[idx] = v;
        }
    }
    // Load W2 (4096 float4)
    {
        const float4* w4g = reinterpret_cast<const float4*>(W2);
        float4* w4s = reinterpret_cast<float4*>(w_s);
        #pragma unroll
        for (int it = 0; it < (FF * FF / 4) / 256; it++) {
            int idx = tid + it * 256;
            w4s[idx] = w4g[idx];
        }
    }
    __syncthreads();

    u64 acc[8][2];
    #pragma unroll
    for (int j = 0; j < 8; j++) {
        acc[j][0] = pk2(0.f, 0.f);
        acc[j][1] = pk2(0.f, 0.f);
    }

    const float4* a4s = reinterpret_cast<const float4*>(a_s);
    const float4* w4s = reinterpret_cast<const float4*>(w_s);

    #pragma unroll 4
    for (int k = 0; k < FF; k += 4) {
        float4 wv0 = w4s[(k + 0) * 32 + tx];
        float4 wv1 = w4s[(k + 1) * 32 + tx];
        float4 wv2 = w4s[(k + 2) * 32 + tx];
        float4 wv3 = w4s[(k + 3) * 32 + tx];
        u64 w0lo = pk2(wv0.x, wv0.y), w0hi = pk2(wv0.z, wv0.w);
        u64 w1lo = pk2(wv1.x, wv1.y), w1hi = pk2(wv1.z, wv1.w);
        u64 w2lo = pk2(wv2.x, wv2.y), w2hi = pk2(wv2.z, wv2.w);
        u64 w3lo = pk2(wv3.x, wv3.y), w3hi = pk2(wv3.z, wv3.w);

        #pragma unroll
        for (int j = 0; j < 8; j++) {
            int r = ty * 8 + j;
            float4 av = a4s[r * 32 + (k >> 2)];
            u64 ax = pk2(av.x, av.x);
            u64 ay = pk2(av.y, av.y);
            u64 az = pk2(av.z, av.z);
            u64 aw = pk2(av.w, av.w);
            fma2(acc[j][0], ax, w0lo);  fma2(acc[j][1], ax, w0hi);
            fma2(acc[j][0], ay, w1lo);  fma2(acc[j][1], ay, w1hi);
            fma2(acc[j][0], az, w2lo);  fma2(acc[j][1], az, w2hi);
            fma2(acc[j][0], aw, w3lo);  fma2(acc[j][1], aw, w3hi);
        }
    }

    // Epilogue: + b2, write float4
    float4 bias = reinterpret_cast<const float4*>(b2)[tx];
    #pragma unroll
    for (int j = 0; j < 8; j++) {
        int gr = row0 + ty * 8 + j;
        if (gr < NN) {
            float4 o;
            upk2(o.x, o.y, acc[j][0]);
            upk2(o.z, o.w, acc[j][1]);
            o.x += bias.x; o.y += bias.y; o.z += bias.z; o.w += bias.w;
            reinterpret_cast<float4*>(out)[(size_t)gr * 32 + tx] = o;
        }
    }
}

// ---------------------------------------------------------------------------
// Launch: init+detect -> link -> gather -> gemm (capturable, 4 launches)
// Inputs (metadata order): x, edge_index, edge_weight, W1, b1, W2, b2, a, b
// ---------------------------------------------------------------------------
extern "C" void kernel_launch(void* const* d_in, const int* in_sizes, int n_in,
                              void* d_out, int out_size) {
    const float* x   = (const float*)d_in[0];
    const void*  ei  = d_in[1];
    const float* W2  = (const float*)d_in[5];
    const float* b2  = (const float*)d_in[6];
    float*       out = (float*)d_out;

    float* agg = nullptr;
    cudaGetSymbolAddress((void**)&agg, g_agg);

    init_detect_kernel<<<(NN + 255) / 256, 256>>>((const unsigned int*)ei);

    link_kernel<<<(EE + 255) / 256, 256>>>(ei);

    {
        int warps = GATHER_SPAN;                       // 12500 warps
        int blocks = (warps * 32 + 255) / 256;         // 1563
        gather_kernel<<<blocks, 256>>>(x, ei, agg);
    }

    {
        int smem_bytes = (GEMM_ROWS * FF + FF * FF) * sizeof(float);  // 96 KB
        cudaFuncSetAttribute(gemm_kernel,
                             cudaFuncAttributeMaxDynamicSharedMemorySize,
                             smem_bytes);
        int blocks = (NN + GEMM_ROWS - 1) / GEMM_ROWS;  // 782
        gemm_kernel<<<blocks, 256, smem_bytes>>>(agg, W2, b2, out);
    }
}